// round 14
// baseline (speedup 1.0000x reference)
#include <cuda_runtime.h>
#include <cuda_fp16.h>
#include <cstdint>

// Problem constants
#define SQ    4096
#define HIDN  1024
#define NH    16
#define HD    64
#define NEGV  -1e30f
#define QSCALE 0.125f

// fp16 copies of inputs (converted once per call)
__device__ __half g_X [SQ * HIDN];
__device__ __half g_WQ[HIDN * HIDN];
__device__ __half g_WK[HIDN * HIDN];
__device__ __half g_WV[HIDN * HIDN];
// Projection outputs (g_K/g_V are key-compacted)
__device__ __half g_Q[SQ * HIDN];
__device__ __half g_K[SQ * HIDN];
__device__ __half g_V[SQ * HIDN];
// Mask compaction
__device__ int g_idx[SQ];
__device__ int g_nv;

__device__ __forceinline__ void mma_f16(float* c,
                                        uint32_t a0, uint32_t a1, uint32_t a2, uint32_t a3,
                                        uint32_t b0, uint32_t b1)
{
    asm volatile(
        "mma.sync.aligned.m16n8k16.row.col.f32.f16.f16.f32 "
        "{%0,%1,%2,%3}, {%4,%5,%6,%7}, {%8,%9}, {%0,%1,%2,%3};"
        : "+f"(c[0]), "+f"(c[1]), "+f"(c[2]), "+f"(c[3])
        : "r"(a0), "r"(a1), "r"(a2), "r"(a3), "r"(b0), "r"(b1));
}

__device__ __forceinline__ void ldsm_x4(uint32_t& r0, uint32_t& r1, uint32_t& r2, uint32_t& r3,
                                        uint32_t addr)
{
    asm volatile("ldmatrix.sync.aligned.m8n8.x4.shared.b16 {%0,%1,%2,%3}, [%4];"
                 : "=r"(r0), "=r"(r1), "=r"(r2), "=r"(r3) : "r"(addr));
}
__device__ __forceinline__ void ldsm_x4_t(uint32_t& r0, uint32_t& r1, uint32_t& r2, uint32_t& r3,
                                          uint32_t addr)
{
    asm volatile("ldmatrix.sync.aligned.m8n8.x4.trans.shared.b16 {%0,%1,%2,%3}, [%4];"
                 : "=r"(r0), "=r"(r1), "=r"(r2), "=r"(r3) : "r"(addr));
}
__device__ __forceinline__ uint32_t smem_u32(const void* p) {
    uint32_t a;
    asm("{ .reg .u64 t; cvta.to.shared.u64 t, %1; cvt.u32.u64 %0, t; }" : "=r"(a) : "l"(p));
    return a;
}
__device__ __forceinline__ void cp16(uint32_t saddr, const void* g) {
    asm volatile("cp.async.cg.shared.global [%0], [%1], 16;" :: "r"(saddr), "l"(g));
}
#define CP_COMMIT() asm volatile("cp.async.commit_group;" ::: "memory")
#define CP_WAIT(N)  asm volatile("cp.async.wait_group %0;" :: "n"(N) : "memory")

// ===========================================================================
// Fused fp32->fp16 conversion (blocks 0..N-2) + mask compaction (last block).
// ===========================================================================
#define N4X (SQ * HIDN / 4)
#define N4W (HIDN * HIDN / 4)

__global__ __launch_bounds__(256)
void cvt_compact_kernel(const float* __restrict__ x,  const float* __restrict__ Wq,
                        const float* __restrict__ Wk, const float* __restrict__ Wv,
                        const int* __restrict__ mask)
{
    if (blockIdx.x == gridDim.x - 1) {
        __shared__ int wsum[8];
        const int t    = threadIdx.x;
        const int lane = t & 31;
        const int wid  = t >> 5;

        int mbits[16];
        int s = 0;
        #pragma unroll
        for (int i = 0; i < 16; i++) {
            int mm = mask[t * 16 + i] != 0;
            mbits[i] = mm;
            s += mm;
        }
        #pragma unroll
        for (int i = 0; i < 16; i++) g_idx[t * 16 + i] = 0;

        int sc = s;
        #pragma unroll
        for (int off = 1; off < 32; off <<= 1) {
            int v = __shfl_up_sync(0xffffffffu, sc, off);
            if (lane >= off) sc += v;
        }
        if (lane == 31) wsum[wid] = sc;
        __syncthreads();
        int wb = 0;
        for (int w = 0; w < wid; w++) wb += wsum[w];
        int pos = wb + sc - s;
        #pragma unroll
        for (int i = 0; i < 16; i++)
            if (mbits[i]) g_idx[pos++] = t * 16 + i;
        if (t == 255) g_nv = wb + sc;
        return;
    }

    const int nblk  = gridDim.x - 1;
    const int total = N4X + 3 * N4W;
    for (int idx = blockIdx.x * blockDim.x + threadIdx.x; idx < total;
         idx += nblk * blockDim.x) {
        const float* src; __half* dst; int off;
        if (idx < N4X)               { src = x;  dst = g_X;  off = idx; }
        else if (idx < N4X + N4W)    { src = Wq; dst = g_WQ; off = idx - N4X; }
        else if (idx < N4X + 2*N4W)  { src = Wk; dst = g_WK; off = idx - N4X - N4W; }
        else                         { src = Wv; dst = g_WV; off = idx - N4X - 2*N4W; }
        float4 v = ((const float4*)src)[off];
        __half2 h0 = __floats2half2_rn(v.x, v.y);
        __half2 h1 = __floats2half2_rn(v.z, v.w);
        ((uint2*)dst)[off] = make_uint2(*(uint32_t*)&h0, *(uint32_t*)&h1);
    }
}

// ===========================================================================
// QKV GEMM v4: fp16, cp.async ring. z=0: Q over all rows. z=1/2: K/V over
// COMPACTED key rows only (A rows gathered through g_idx; tiles >= nv exit).
// grid = (16, 32, 3), 256 threads. BM=128, BN=64, BK=64. Warp tile 32x32.
// ===========================================================================
#define GST 72
#define G_ABUF 9216
#define G_WBUF 4608
#define GEMM_SMEM_BYTES ((3 * G_ABUF + 3 * G_WBUF) * 2)

__global__ __launch_bounds__(256, 2)
void qkv_mma_kernel(const float* __restrict__ bq,
                    const float* __restrict__ bk,
                    const float* __restrict__ bv)
{
    const __half* Wg;
    const float* bias;
    __half* Y;
    float oscale;
    bool compact;
    if (blockIdx.z == 0)      { Wg = g_WQ; bias = bq; Y = g_Q; oscale = QSCALE; compact = false; }
    else if (blockIdx.z == 1) { Wg = g_WK; bias = bk; Y = g_K; oscale = 1.0f;   compact = true; }
    else                      { Wg = g_WV; bias = bv; Y = g_V; oscale = 1.0f;   compact = true; }

    const int rowBase = blockIdx.y * 128;
    if (compact && rowBase >= g_nv) return;   // whole tile is padding

    extern __shared__ __half gsm[];
    __half* Ab = gsm;
    __half* Wb = gsm + 3 * G_ABUF;

    const int t    = threadIdx.x;
    const int wid  = t >> 5;
    const int lane = t & 31;
    const int g    = lane >> 2;
    const int tg   = lane & 3;
    const int lm   = lane >> 3;
    const int lr   = lane & 7;

    const int colBase = blockIdx.x * 64;
    const int m0  = (wid >> 1) * 32;
    const int n0w = (wid & 1) * 32;

    const int srow = t >> 3;
    const int sc8  = (t & 7) * 8;

    // Loop-invariant source rows for A staging (gathered for K/V)
    int srcrow[4];
    #pragma unroll
    for (int i = 0; i < 4; i++) {
        int r = rowBase + srow + i * 32;
        srcrow[i] = compact ? g_idx[r] : r;
    }

    const uint32_t aoff = (uint32_t)(((m0 + (lm & 1) * 8 + lr) * GST + (lm >> 1) * 8) * 2);
    const uint32_t boff = (uint32_t)((((lm & 1) * 8 + lr) * GST + n0w + (lm >> 1) * 8) * 2);

    float acc[2][4][4] = {};

    #define STG(buf, kk) do {                                                       \
        uint32_t ad = smem_u32(Ab + (buf) * G_ABUF);                                \
        uint32_t wd = smem_u32(Wb + (buf) * G_WBUF);                                \
        _Pragma("unroll")                                                           \
        for (int i_ = 0; i_ < 4; i_++) {                                            \
            int r_ = srow + i_ * 32;                                                \
            cp16(ad + (uint32_t)((r_ * GST + sc8) * 2),                             \
                 &g_X[srcrow[i_] * HIDN + (kk) + sc8]);                             \
        }                                                                           \
        _Pragma("unroll")                                                           \
        for (int i_ = 0; i_ < 2; i_++) {                                            \
            int r_ = srow + i_ * 32;                                                \
            cp16(wd + (uint32_t)((r_ * GST + sc8) * 2),                             \
                 &Wg[((kk) + r_) * HIDN + colBase + sc8]);                          \
        }                                                                           \
    } while (0)

    STG(0, 0);  CP_COMMIT();
    STG(1, 64); CP_COMMIT();

    #pragma unroll 1
    for (int it = 0; it < HIDN / 64; it++) {
        const int buf = it % 3;
        CP_WAIT(1);
        __syncthreads();
        if (it + 2 < HIDN / 64) STG((it + 2) % 3, (it + 2) * 64);
        CP_COMMIT();

        const uint32_t ab = smem_u32(Ab + buf * G_ABUF) + aoff;
        const uint32_t bb = smem_u32(Wb + buf * G_WBUF) + boff;

        #pragma unroll
        for (int s = 0; s < 4; s++) {
            uint32_t a[2][4];
            #pragma unroll
            for (int mi = 0; mi < 2; mi++)
                ldsm_x4(a[mi][0], a[mi][1], a[mi][2], a[mi][3],
                        ab + (uint32_t)(((mi * 16) * GST + s * 16) * 2));
            #pragma unroll
            for (int j2 = 0; j2 < 2; j2++) {
                uint32_t b0, b1, b2, b3;
                ldsm_x4_t(b0, b1, b2, b3,
                          bb + (uint32_t)(((s * 16) * GST + j2 * 16) * 2));
                #pragma unroll
                for (int mi = 0; mi < 2; mi++) {
                    mma_f16(acc[mi][j2 * 2],     a[mi][0], a[mi][1], a[mi][2], a[mi][3], b0, b1);
                    mma_f16(acc[mi][j2 * 2 + 1], a[mi][0], a[mi][1], a[mi][2], a[mi][3], b2, b3);
                }
            }
        }
    }
    #undef STG

    #pragma unroll
    for (int mi = 0; mi < 2; mi++) {
        #pragma unroll
        for (int j = 0; j < 4; j++) {
            int c = colBase + n0w + j * 8 + 2 * tg;
            float2 bb = *(const float2*)&bias[c];
            int r0 = rowBase + m0 + mi * 16 + g;
            __half2 h0 = __floats2half2_rn((acc[mi][j][0] + bb.x) * oscale,
                                           (acc[mi][j][1] + bb.y) * oscale);
            __half2 h1 = __floats2half2_rn((acc[mi][j][2] + bb.x) * oscale,
                                           (acc[mi][j][3] + bb.y) * oscale);
            *(uint32_t*)&Y[r0 * HIDN + c]       = *(uint32_t*)&h0;
            *(uint32_t*)&Y[(r0 + 8) * HIDN + c] = *(uint32_t*)&h1;
        }
    }
}

// ===========================================================================
// Flash attention v10: pre-compacted K/V (contiguous rows), fp32 __expf
// softmax, mask only on tail tile. 4 warps x 32 q-rows, grid = (S/128, H).
// ===========================================================================
#define KST 72
#define F_KBUF 4608
#define FLASH_SMEM_BYTES (3 * F_KBUF * 2 * 2)

__global__ __launch_bounds__(128, 3)
void flash_mma(float* __restrict__ out)
{
    extern __shared__ char fsm[];
    __half* Kb = (__half*)fsm;                       // 3 x 4608 halfs
    __half* Vb = (__half*)(fsm + 3 * F_KBUF * 2);    // 3 x 4608 halfs

    const int t    = threadIdx.x;
    const int wid  = t >> 5;
    const int lane = t & 31;
    const int g    = lane >> 2;
    const int tg   = lane & 3;
    const int lm   = lane >> 3;
    const int lr   = lane & 7;
    const int h     = blockIdx.y;
    const int qBase = blockIdx.x * 128;
    const int m0    = wid * 32;

    const int srow = t >> 3;          // 0..15
    const int sc8  = (t & 7) * 8;

    const uint32_t koff = (uint32_t)((lr * KST + lm * 8) * 2);
    const uint32_t voff = (uint32_t)((((lm & 1) * 8 + lr) * KST + (lm >> 1) * 8) * 2);

    const int nv  = g_nv;
    const int nts = (nv + 63) >> 6;   // number of 64-key tiles

    // Q fragments, loop-invariant (pre-scaled by QSCALE in projection)
    uint32_t qa[2][4][4];
    #pragma unroll
    for (int mi = 0; mi < 2; mi++) {
        const __half* Q0 = &g_Q[(qBase + m0 + mi * 16 + g) * HIDN + h * HD];
        const __half* Q1 = Q0 + 8 * HIDN;
        #pragma unroll
        for (int s = 0; s < 4; s++) {
            qa[mi][s][0] = *(const uint32_t*)&Q0[s * 16 + 2 * tg];
            qa[mi][s][1] = *(const uint32_t*)&Q1[s * 16 + 2 * tg];
            qa[mi][s][2] = *(const uint32_t*)&Q0[s * 16 + 2 * tg + 8];
            qa[mi][s][3] = *(const uint32_t*)&Q1[s * 16 + 2 * tg + 8];
        }
    }

    float oacc[2][8][4] = {};
    float ls[2][2] = {};

    #define STAGE(buf, kb) do {                                                     \
        uint32_t kdst = smem_u32(Kb + (buf) * F_KBUF);                              \
        uint32_t vdst = smem_u32(Vb + (buf) * F_KBUF);                              \
        _Pragma("unroll")                                                           \
        for (int i_ = 0; i_ < 4; i_++) {                                            \
            int row_ = srow + i_ * 16;                                              \
            cp16(kdst + (uint32_t)((row_ * KST + sc8) * 2),                         \
                 &g_K[((kb) + row_) * HIDN + h * HD + sc8]);                        \
            cp16(vdst + (uint32_t)((row_ * KST + sc8) * 2),                         \
                 &g_V[((kb) + row_) * HIDN + h * HD + sc8]);                        \
        }                                                                           \
    } while (0)

    STAGE(0, 0);  CP_COMMIT();
    STAGE(1, 64); CP_COMMIT();

    #pragma unroll 1
    for (int it = 0; it < nts; it++) {
        const int buf = it % 3;
        CP_WAIT(1);
        __syncthreads();
        if (it + 2 < nts) STAGE((it + 2) % 3, (it + 2) * 64);
        CP_COMMIT();

        const uint32_t kbase = smem_u32(Kb + buf * F_KBUF) + koff;
        const uint32_t vbase = smem_u32(Vb + buf * F_KBUF) + voff;
        const int kb = it * 64;
        const bool tail = (it == nts - 1);

        #pragma unroll
        for (int sp = 0; sp < 4; sp++) {
            float sacc[2][2][4] = {};
            uint32_t pa[2][4];

            #pragma unroll
            for (int jj = 0; jj < 2; jj++) {
                int j = sp * 2 + jj;
                uint32_t kl0, kl1, kl2, kl3, kh0, kh1, kh2, kh3;
                ldsm_x4(kl0, kl1, kl2, kl3, kbase + (uint32_t)((j * 8 * KST) * 2));
                ldsm_x4(kh0, kh1, kh2, kh3, kbase + (uint32_t)((j * 8 * KST + 32) * 2));
                #pragma unroll
                for (int mi = 0; mi < 2; mi++) {
                    mma_f16(sacc[mi][jj], qa[mi][0][0], qa[mi][0][1], qa[mi][0][2], qa[mi][0][3], kl0, kl1);
                    mma_f16(sacc[mi][jj], qa[mi][1][0], qa[mi][1][1], qa[mi][1][2], qa[mi][1][3], kl2, kl3);
                    mma_f16(sacc[mi][jj], qa[mi][2][0], qa[mi][2][1], qa[mi][2][2], qa[mi][2][3], kh0, kh1);
                    mma_f16(sacc[mi][jj], qa[mi][3][0], qa[mi][3][1], qa[mi][3][2], qa[mi][3][3], kh2, kh3);
                }
            }

            // softmax (fp32 __expf); positional mask only on tail tile
            #pragma unroll
            for (int mi = 0; mi < 2; mi++) {
                #pragma unroll
                for (int jj = 0; jj < 2; jj++) {
                    float s0 = sacc[mi][jj][0], s1 = sacc[mi][jj][1];
                    float s2 = sacc[mi][jj][2], s3 = sacc[mi][jj][3];
                    if (tail) {
                        int kc = kb + (sp * 2 + jj) * 8 + 2 * tg;
                        float mk0 = (kc     < nv) ? 0.f : NEGV;
                        float mk1 = (kc + 1 < nv) ? 0.f : NEGV;
                        s0 += mk0; s1 += mk1; s2 += mk0; s3 += mk1;
                    }
                    float p00 = __expf(s0);
                    float p01 = __expf(s1);
                    float p10 = __expf(s2);
                    float p11 = __expf(s3);
                    ls[mi][0] += p00 + p01;
                    ls[mi][1] += p10 + p11;
                    __half2 hA = __floats2half2_rn(p00, p01);   // row g
                    __half2 hB = __floats2half2_rn(p10, p11);   // row g+8
                    pa[mi][jj * 2]     = *(uint32_t*)&hA;
                    pa[mi][jj * 2 + 1] = *(uint32_t*)&hB;
                }
            }

            #pragma unroll
            for (int jd2 = 0; jd2 < 4; jd2++) {
                uint32_t v0, v1, v2, v3;
                ldsm_x4_t(v0, v1, v2, v3,
                          vbase + (uint32_t)(((sp * 16) * KST + jd2 * 16) * 2));
                #pragma unroll
                for (int mi = 0; mi < 2; mi++) {
                    mma_f16(oacc[mi][jd2 * 2],     pa[mi][0], pa[mi][1], pa[mi][2], pa[mi][3], v0, v1);
                    mma_f16(oacc[mi][jd2 * 2 + 1], pa[mi][0], pa[mi][1], pa[mi][2], pa[mi][3], v2, v3);
                }
            }
        }
    }
    #undef STAGE
    CP_WAIT(0);

    #pragma unroll
    for (int mi = 0; mi < 2; mi++) {
        #pragma unroll
        for (int off = 1; off <= 2; off <<= 1) {
            ls[mi][0] += __shfl_xor_sync(0xffffffffu, ls[mi][0], off);
            ls[mi][1] += __shfl_xor_sync(0xffffffffu, ls[mi][1], off);
        }
        float inv0 = 1.0f / ls[mi][0];
        float inv1 = 1.0f / ls[mi][1];
        float* o0 = &out[(qBase + m0 + mi * 16 + g) * HIDN + h * HD];
        float* o1 = o0 + 8 * HIDN;
        #pragma unroll
        for (int jd = 0; jd < 8; jd++) {
            int dc = jd * 8 + 2 * tg;
            *(float2*)&o0[dc] = make_float2(oacc[mi][jd][0] * inv0, oacc[mi][jd][1] * inv0);
            *(float2*)&o1[dc] = make_float2(oacc[mi][jd][2] * inv1, oacc[mi][jd][3] * inv1);
        }
    }
}

// ---------------------------------------------------------------------------
// kernel_launch
// Inputs: hidden_states, attention_mask, Wq, bq, Wk, bk, Wv, bv
// ---------------------------------------------------------------------------
extern "C" void kernel_launch(void* const* d_in, const int* in_sizes, int n_in,
                              void* d_out, int out_size)
{
    const float* x    = (const float*)d_in[0];
    const int*   msk  = (const int*)  d_in[1];
    const float* Wq   = (const float*)d_in[2];
    const float* bq   = (const float*)d_in[3];
    const float* Wk   = (const float*)d_in[4];
    const float* bk   = (const float*)d_in[5];
    const float* Wv   = (const float*)d_in[6];
    const float* bv   = (const float*)d_in[7];
    float* out = (float*)d_out;

    cudaFuncSetAttribute(qkv_mma_kernel,
                         cudaFuncAttributeMaxDynamicSharedMemorySize, GEMM_SMEM_BYTES);
    cudaFuncSetAttribute(flash_mma,
                         cudaFuncAttributeMaxDynamicSharedMemorySize, FLASH_SMEM_BYTES);

    cvt_compact_kernel<<<2049, 256>>>(x, Wq, Wk, Wv, msk);

    dim3 ggrid(HIDN / 64, SQ / 128, 3);
    qkv_mma_kernel<<<ggrid, 256, GEMM_SMEM_BYTES>>>(bq, bk, bv);

    dim3 agrid(SQ / 128, NH);
    flash_mma<<<agrid, 128, FLASH_SMEM_BYTES>>>(out);
}

// round 15
// speedup vs baseline: 1.3096x; 1.3096x over previous
#include <cuda_runtime.h>
#include <cuda_fp16.h>
#include <cstdint>

// Problem constants
#define SQ    4096
#define HIDN  1024
#define NH    16
#define HD    64
#define NEGV  -1e30f
#define QSCALE 0.125f

// fp16 copies of inputs (converted once per call)
__device__ __half g_X [SQ * HIDN];
__device__ __half g_WQ[HIDN * HIDN];
__device__ __half g_WK[HIDN * HIDN];
__device__ __half g_WV[HIDN * HIDN];
// Projection outputs
__device__ __half g_Q[SQ * HIDN];
__device__ __half g_K[SQ * HIDN];
__device__ __half g_V[SQ * HIDN];
// Mask compaction
__device__ int g_idx[SQ];
__device__ int g_nv;

__device__ __forceinline__ void mma_f16(float* c,
                                        uint32_t a0, uint32_t a1, uint32_t a2, uint32_t a3,
                                        uint32_t b0, uint32_t b1)
{
    asm volatile(
        "mma.sync.aligned.m16n8k16.row.col.f32.f16.f16.f32 "
        "{%0,%1,%2,%3}, {%4,%5,%6,%7}, {%8,%9}, {%0,%1,%2,%3};"
        : "+f"(c[0]), "+f"(c[1]), "+f"(c[2]), "+f"(c[3])
        : "r"(a0), "r"(a1), "r"(a2), "r"(a3), "r"(b0), "r"(b1));
}

__device__ __forceinline__ void ldsm_x4(uint32_t& r0, uint32_t& r1, uint32_t& r2, uint32_t& r3,
                                        uint32_t addr)
{
    asm volatile("ldmatrix.sync.aligned.m8n8.x4.shared.b16 {%0,%1,%2,%3}, [%4];"
                 : "=r"(r0), "=r"(r1), "=r"(r2), "=r"(r3) : "r"(addr));
}
__device__ __forceinline__ void ldsm_x4_t(uint32_t& r0, uint32_t& r1, uint32_t& r2, uint32_t& r3,
                                          uint32_t addr)
{
    asm volatile("ldmatrix.sync.aligned.m8n8.x4.trans.shared.b16 {%0,%1,%2,%3}, [%4];"
                 : "=r"(r0), "=r"(r1), "=r"(r2), "=r"(r3) : "r"(addr));
}
__device__ __forceinline__ uint32_t smem_u32(const void* p) {
    uint32_t a;
    asm("{ .reg .u64 t; cvta.to.shared.u64 t, %1; cvt.u32.u64 %0, t; }" : "=r"(a) : "l"(p));
    return a;
}
__device__ __forceinline__ void cp16(uint32_t saddr, const void* g) {
    asm volatile("cp.async.cg.shared.global [%0], [%1], 16;" :: "r"(saddr), "l"(g));
}
#define CP_COMMIT() asm volatile("cp.async.commit_group;" ::: "memory")
#define CP_WAIT(N)  asm volatile("cp.async.wait_group %0;" :: "n"(N) : "memory")

// ===========================================================================
// Fused fp32->fp16 conversion (blocks 0..N-2) + mask compaction (last block).
// ===========================================================================
#define N4X (SQ * HIDN / 4)
#define N4W (HIDN * HIDN / 4)

__global__ __launch_bounds__(256)
void cvt_compact_kernel(const float* __restrict__ x,  const float* __restrict__ Wq,
                        const float* __restrict__ Wk, const float* __restrict__ Wv,
                        const int* __restrict__ mask)
{
    if (blockIdx.x == gridDim.x - 1) {
        __shared__ int wsum[8];
        const int t    = threadIdx.x;
        const int lane = t & 31;
        const int wid  = t >> 5;

        int mbits[16];
        int s = 0;
        #pragma unroll
        for (int i = 0; i < 16; i++) {
            int mm = mask[t * 16 + i] != 0;
            mbits[i] = mm;
            s += mm;
        }
        #pragma unroll
        for (int i = 0; i < 16; i++) g_idx[t * 16 + i] = 0;

        int sc = s;
        #pragma unroll
        for (int off = 1; off < 32; off <<= 1) {
            int v = __shfl_up_sync(0xffffffffu, sc, off);
            if (lane >= off) sc += v;
        }
        if (lane == 31) wsum[wid] = sc;
        __syncthreads();
        int wb = 0;
        for (int w = 0; w < wid; w++) wb += wsum[w];
        int pos = wb + sc - s;
        #pragma unroll
        for (int i = 0; i < 16; i++)
            if (mbits[i]) g_idx[pos++] = t * 16 + i;
        if (t == 255) g_nv = wb + sc;
        return;
    }

    const int nblk  = gridDim.x - 1;
    const int total = N4X + 3 * N4W;
    for (int idx = blockIdx.x * blockDim.x + threadIdx.x; idx < total;
         idx += nblk * blockDim.x) {
        const float* src; __half* dst; int off;
        if (idx < N4X)               { src = x;  dst = g_X;  off = idx; }
        else if (idx < N4X + N4W)    { src = Wq; dst = g_WQ; off = idx - N4X; }
        else if (idx < N4X + 2*N4W)  { src = Wk; dst = g_WK; off = idx - N4X - N4W; }
        else                         { src = Wv; dst = g_WV; off = idx - N4X - 2*N4W; }
        float4 v = ((const float4*)src)[off];
        __half2 h0 = __floats2half2_rn(v.x, v.y);
        __half2 h1 = __floats2half2_rn(v.z, v.w);
        ((uint2*)dst)[off] = make_uint2(*(uint32_t*)&h0, *(uint32_t*)&h1);
    }
}

// ===========================================================================
// QKV GEMM v3 (round-12 version, full rows, no compaction).
// grid = (16, 32, 3), 256 threads. BM=128, BN=64, BK=64. Warp tile 32x32.
// ===========================================================================
#define GST 72
#define G_ABUF 9216
#define G_WBUF 4608
#define GEMM_SMEM_BYTES ((3 * G_ABUF + 3 * G_WBUF) * 2)

__global__ __launch_bounds__(256, 2)
void qkv_mma_kernel(const float* __restrict__ bq,
                    const float* __restrict__ bk,
                    const float* __restrict__ bv)
{
    const __half* Wg;
    const float* bias;
    __half* Y;
    float oscale;
    if (blockIdx.z == 0)      { Wg = g_WQ; bias = bq; Y = g_Q; oscale = QSCALE; }
    else if (blockIdx.z == 1) { Wg = g_WK; bias = bk; Y = g_K; oscale = 1.0f; }
    else                      { Wg = g_WV; bias = bv; Y = g_V; oscale = 1.0f; }

    extern __shared__ __half gsm[];
    __half* Ab = gsm;
    __half* Wb = gsm + 3 * G_ABUF;

    const int t    = threadIdx.x;
    const int wid  = t >> 5;
    const int lane = t & 31;
    const int g    = lane >> 2;
    const int tg   = lane & 3;
    const int lm   = lane >> 3;
    const int lr   = lane & 7;

    const int rowBase = blockIdx.y * 128;
    const int colBase = blockIdx.x * 64;
    const int m0  = (wid >> 1) * 32;
    const int n0w = (wid & 1) * 32;

    const int srow = t >> 3;
    const int sc8  = (t & 7) * 8;

    const uint32_t aoff = (uint32_t)(((m0 + (lm & 1) * 8 + lr) * GST + (lm >> 1) * 8) * 2);
    const uint32_t boff = (uint32_t)((((lm & 1) * 8 + lr) * GST + n0w + (lm >> 1) * 8) * 2);

    float acc[2][4][4] = {};

    #define STG(buf, kk) do {                                                       \
        uint32_t ad = smem_u32(Ab + (buf) * G_ABUF);                                \
        uint32_t wd = smem_u32(Wb + (buf) * G_WBUF);                                \
        _Pragma("unroll")                                                           \
        for (int i_ = 0; i_ < 4; i_++) {                                            \
            int r_ = srow + i_ * 32;                                                \
            cp16(ad + (uint32_t)((r_ * GST + sc8) * 2),                             \
                 &g_X[(rowBase + r_) * HIDN + (kk) + sc8]);                         \
        }                                                                           \
        _Pragma("unroll")                                                           \
        for (int i_ = 0; i_ < 2; i_++) {                                            \
            int r_ = srow + i_ * 32;                                                \
            cp16(wd + (uint32_t)((r_ * GST + sc8) * 2),                             \
                 &Wg[((kk) + r_) * HIDN + colBase + sc8]);                          \
        }                                                                           \
    } while (0)

    STG(0, 0);  CP_COMMIT();
    STG(1, 64); CP_COMMIT();

    #pragma unroll 1
    for (int it = 0; it < HIDN / 64; it++) {
        const int buf = it % 3;
        CP_WAIT(1);
        __syncthreads();
        if (it + 2 < HIDN / 64) STG((it + 2) % 3, (it + 2) * 64);
        CP_COMMIT();

        const uint32_t ab = smem_u32(Ab + buf * G_ABUF) + aoff;
        const uint32_t bb = smem_u32(Wb + buf * G_WBUF) + boff;

        #pragma unroll
        for (int s = 0; s < 4; s++) {
            uint32_t a[2][4];
            #pragma unroll
            for (int mi = 0; mi < 2; mi++)
                ldsm_x4(a[mi][0], a[mi][1], a[mi][2], a[mi][3],
                        ab + (uint32_t)(((mi * 16) * GST + s * 16) * 2));
            #pragma unroll
            for (int j2 = 0; j2 < 2; j2++) {
                uint32_t b0, b1, b2, b3;
                ldsm_x4_t(b0, b1, b2, b3,
                          bb + (uint32_t)(((s * 16) * GST + j2 * 16) * 2));
                #pragma unroll
                for (int mi = 0; mi < 2; mi++) {
                    mma_f16(acc[mi][j2 * 2],     a[mi][0], a[mi][1], a[mi][2], a[mi][3], b0, b1);
                    mma_f16(acc[mi][j2 * 2 + 1], a[mi][0], a[mi][1], a[mi][2], a[mi][3], b2, b3);
                }
            }
        }
    }
    #undef STG

    #pragma unroll
    for (int mi = 0; mi < 2; mi++) {
        #pragma unroll
        for (int j = 0; j < 4; j++) {
            int c = colBase + n0w + j * 8 + 2 * tg;
            float2 bb = *(const float2*)&bias[c];
            int r0 = rowBase + m0 + mi * 16 + g;
            __half2 h0 = __floats2half2_rn((acc[mi][j][0] + bb.x) * oscale,
                                           (acc[mi][j][1] + bb.y) * oscale);
            __half2 h1 = __floats2half2_rn((acc[mi][j][2] + bb.x) * oscale,
                                           (acc[mi][j][3] + bb.y) * oscale);
            *(uint32_t*)&Y[r0 * HIDN + c]       = *(uint32_t*)&h0;
            *(uint32_t*)&Y[(r0 + 8) * HIDN + c] = *(uint32_t*)&h1;
        }
    }
}

// ===========================================================================
// Flash attention v11: 64 q-rows/CTA (4 warps x 16q) for occupancy + balance,
// compacted keys via g_idx gather, fp32 __expf, mask only on tail tile.
// grid = (S/64, H), 128 threads, 4 CTAs/SM.
// ===========================================================================
#define KST 72
#define F_KBUF 4608
#define FLASH_SMEM_BYTES (3 * F_KBUF * 2 * 2)

__global__ __launch_bounds__(128, 4)
void flash_mma(float* __restrict__ out)
{
    extern __shared__ char fsm[];
    __half* Kb = (__half*)fsm;                       // 3 x 4608 halfs
    __half* Vb = (__half*)(fsm + 3 * F_KBUF * 2);    // 3 x 4608 halfs

    const int t    = threadIdx.x;
    const int wid  = t >> 5;
    const int lane = t & 31;
    const int g    = lane >> 2;
    const int tg   = lane & 3;
    const int lm   = lane >> 3;
    const int lr   = lane & 7;
    const int h     = blockIdx.y;
    const int qBase = blockIdx.x * 64;
    const int m0    = wid * 16;

    const int srow = t >> 3;          // 0..15
    const int sc8  = (t & 7) * 8;

    const uint32_t koff = (uint32_t)((lr * KST + lm * 8) * 2);
    const uint32_t voff = (uint32_t)((((lm & 1) * 8 + lr) * KST + (lm >> 1) * 8) * 2);

    const int nv  = g_nv;
    const int nts = (nv + 63) >> 6;   // number of 64-key tiles

    // Q fragments, loop-invariant (pre-scaled by QSCALE in projection)
    uint32_t qa[4][4];
    {
        const __half* Q0 = &g_Q[(qBase + m0 + g) * HIDN + h * HD];
        const __half* Q1 = Q0 + 8 * HIDN;
        #pragma unroll
        for (int s = 0; s < 4; s++) {
            qa[s][0] = *(const uint32_t*)&Q0[s * 16 + 2 * tg];
            qa[s][1] = *(const uint32_t*)&Q1[s * 16 + 2 * tg];
            qa[s][2] = *(const uint32_t*)&Q0[s * 16 + 2 * tg + 8];
            qa[s][3] = *(const uint32_t*)&Q1[s * 16 + 2 * tg + 8];
        }
    }

    float oacc[8][4] = {};
    float ls[2] = {};

    #define STAGE(buf, kb) do {                                                     \
        uint32_t kdst = smem_u32(Kb + (buf) * F_KBUF);                              \
        uint32_t vdst = smem_u32(Vb + (buf) * F_KBUF);                              \
        _Pragma("unroll")                                                           \
        for (int i_ = 0; i_ < 4; i_++) {                                            \
            int row_ = srow + i_ * 16;                                              \
            int src_ = g_idx[(kb) + row_];                                          \
            cp16(kdst + (uint32_t)((row_ * KST + sc8) * 2),                         \
                 &g_K[src_ * HIDN + h * HD + sc8]);                                 \
            cp16(vdst + (uint32_t)((row_ * KST + sc8) * 2),                         \
                 &g_V[src_ * HIDN + h * HD + sc8]);                                 \
        }                                                                           \
    } while (0)

    STAGE(0, 0);  CP_COMMIT();
    STAGE(1, 64); CP_COMMIT();

    #pragma unroll 1
    for (int it = 0; it < nts; it++) {
        const int buf = it % 3;
        CP_WAIT(1);
        __syncthreads();
        if (it + 2 < nts) STAGE((it + 2) % 3, (it + 2) * 64);
        CP_COMMIT();

        const uint32_t kbase = smem_u32(Kb + buf * F_KBUF) + koff;
        const uint32_t vbase = smem_u32(Vb + buf * F_KBUF) + voff;
        const int kb = it * 64;
        const bool tail = (it == nts - 1);

        #pragma unroll
        for (int sp = 0; sp < 4; sp++) {
            float sacc[2][4] = {};
            uint32_t pa[4];

            #pragma unroll
            for (int jj = 0; jj < 2; jj++) {
                int j = sp * 2 + jj;
                uint32_t kl0, kl1, kl2, kl3, kh0, kh1, kh2, kh3;
                ldsm_x4(kl0, kl1, kl2, kl3, kbase + (uint32_t)((j * 8 * KST) * 2));
                ldsm_x4(kh0, kh1, kh2, kh3, kbase + (uint32_t)((j * 8 * KST + 32) * 2));
                mma_f16(sacc[jj], qa[0][0], qa[0][1], qa[0][2], qa[0][3], kl0, kl1);
                mma_f16(sacc[jj], qa[1][0], qa[1][1], qa[1][2], qa[1][3], kl2, kl3);
                mma_f16(sacc[jj], qa[2][0], qa[2][1], qa[2][2], qa[2][3], kh0, kh1);
                mma_f16(sacc[jj], qa[3][0], qa[3][1], qa[3][2], qa[3][3], kh2, kh3);
            }

            // softmax (fp32 __expf); positional mask only on tail tile
            #pragma unroll
            for (int jj = 0; jj < 2; jj++) {
                float s0 = sacc[jj][0], s1 = sacc[jj][1];
                float s2 = sacc[jj][2], s3 = sacc[jj][3];
                if (tail) {
                    int kc = kb + (sp * 2 + jj) * 8 + 2 * tg;
                    float mk0 = (kc     < nv) ? 0.f : NEGV;
                    float mk1 = (kc + 1 < nv) ? 0.f : NEGV;
                    s0 += mk0; s1 += mk1; s2 += mk0; s3 += mk1;
                }
                float p00 = __expf(s0);
                float p01 = __expf(s1);
                float p10 = __expf(s2);
                float p11 = __expf(s3);
                ls[0] += p00 + p01;
                ls[1] += p10 + p11;
                __half2 hA = __floats2half2_rn(p00, p01);   // row g
                __half2 hB = __floats2half2_rn(p10, p11);   // row g+8
                pa[jj * 2]     = *(uint32_t*)&hA;
                pa[jj * 2 + 1] = *(uint32_t*)&hB;
            }

            #pragma unroll
            for (int jd2 = 0; jd2 < 4; jd2++) {
                uint32_t v0, v1, v2, v3;
                ldsm_x4_t(v0, v1, v2, v3,
                          vbase + (uint32_t)(((sp * 16) * KST + jd2 * 16) * 2));
                mma_f16(oacc[jd2 * 2],     pa[0], pa[1], pa[2], pa[3], v0, v1);
                mma_f16(oacc[jd2 * 2 + 1], pa[0], pa[1], pa[2], pa[3], v2, v3);
            }
        }
    }
    #undef STAGE
    CP_WAIT(0);

    // Reduce l across the 4 lanes sharing a row, normalize, store
    #pragma unroll
    for (int off = 1; off <= 2; off <<= 1) {
        ls[0] += __shfl_xor_sync(0xffffffffu, ls[0], off);
        ls[1] += __shfl_xor_sync(0xffffffffu, ls[1], off);
    }
    float inv0 = 1.0f / ls[0];
    float inv1 = 1.0f / ls[1];
    float* o0 = &out[(qBase + m0 + g) * HIDN + h * HD];
    float* o1 = o0 + 8 * HIDN;
    #pragma unroll
    for (int jd = 0; jd < 8; jd++) {
        int dc = jd * 8 + 2 * tg;
        *(float2*)&o0[dc] = make_float2(oacc[jd][0] * inv0, oacc[jd][1] * inv0);
        *(float2*)&o1[dc] = make_float2(oacc[jd][2] * inv1, oacc[jd][3] * inv1);
    }
}

// ---------------------------------------------------------------------------
// kernel_launch
// Inputs: hidden_states, attention_mask, Wq, bq, Wk, bk, Wv, bv
// ---------------------------------------------------------------------------
extern "C" void kernel_launch(void* const* d_in, const int* in_sizes, int n_in,
                              void* d_out, int out_size)
{
    const float* x    = (const float*)d_in[0];
    const int*   msk  = (const int*)  d_in[1];
    const float* Wq   = (const float*)d_in[2];
    const float* bq   = (const float*)d_in[3];
    const float* Wk   = (const float*)d_in[4];
    const float* bk   = (const float*)d_in[5];
    const float* Wv   = (const float*)d_in[6];
    const float* bv   = (const float*)d_in[7];
    float* out = (float*)d_out;

    cudaFuncSetAttribute(qkv_mma_kernel,
                         cudaFuncAttributeMaxDynamicSharedMemorySize, GEMM_SMEM_BYTES);
    cudaFuncSetAttribute(flash_mma,
                         cudaFuncAttributeMaxDynamicSharedMemorySize, FLASH_SMEM_BYTES);

    cvt_compact_kernel<<<2049, 256>>>(x, Wq, Wk, Wv, msk);

    dim3 ggrid(HIDN / 64, SQ / 128, 3);
    qkv_mma_kernel<<<ggrid, 256, GEMM_SMEM_BYTES>>>(bq, bk, bv);

    dim3 agrid(SQ / 64, NH);
    flash_mma<<<agrid, 128, FLASH_SMEM_BYTES>>>(out);
}

// round 16
// speedup vs baseline: 1.3189x; 1.0071x over previous
#include <cuda_runtime.h>
#include <cuda_fp16.h>
#include <cstdint>

// Problem constants
#define SQ    4096
#define HIDN  1024
#define NH    16
#define HD    64
#define NEGV  -1e30f
#define QSCALE 0.125f

// fp16 copies of inputs (converted once per call)
__device__ __half g_X [SQ * HIDN];
__device__ __half g_WQ[HIDN * HIDN];
__device__ __half g_WK[HIDN * HIDN];
__device__ __half g_WV[HIDN * HIDN];
// Projection outputs
__device__ __half g_Q[SQ * HIDN];
__device__ __half g_K[SQ * HIDN];
__device__ __half g_V[SQ * HIDN];
// Mask compaction
__device__ int g_idx[SQ];
__device__ int g_nv;

__device__ __forceinline__ void mma_f16(float* c,
                                        uint32_t a0, uint32_t a1, uint32_t a2, uint32_t a3,
                                        uint32_t b0, uint32_t b1)
{
    asm volatile(
        "mma.sync.aligned.m16n8k16.row.col.f32.f16.f16.f32 "
        "{%0,%1,%2,%3}, {%4,%5,%6,%7}, {%8,%9}, {%0,%1,%2,%3};"
        : "+f"(c[0]), "+f"(c[1]), "+f"(c[2]), "+f"(c[3])
        : "r"(a0), "r"(a1), "r"(a2), "r"(a3), "r"(b0), "r"(b1));
}

__device__ __forceinline__ void ldsm_x4(uint32_t& r0, uint32_t& r1, uint32_t& r2, uint32_t& r3,
                                        uint32_t addr)
{
    asm volatile("ldmatrix.sync.aligned.m8n8.x4.shared.b16 {%0,%1,%2,%3}, [%4];"
                 : "=r"(r0), "=r"(r1), "=r"(r2), "=r"(r3) : "r"(addr));
}
__device__ __forceinline__ void ldsm_x4_t(uint32_t& r0, uint32_t& r1, uint32_t& r2, uint32_t& r3,
                                          uint32_t addr)
{
    asm volatile("ldmatrix.sync.aligned.m8n8.x4.trans.shared.b16 {%0,%1,%2,%3}, [%4];"
                 : "=r"(r0), "=r"(r1), "=r"(r2), "=r"(r3) : "r"(addr));
}
__device__ __forceinline__ uint32_t smem_u32(const void* p) {
    uint32_t a;
    asm("{ .reg .u64 t; cvta.to.shared.u64 t, %1; cvt.u32.u64 %0, t; }" : "=r"(a) : "l"(p));
    return a;
}
__device__ __forceinline__ void cp16(uint32_t saddr, const void* g) {
    asm volatile("cp.async.cg.shared.global [%0], [%1], 16;" :: "r"(saddr), "l"(g));
}
#define CP_COMMIT() asm volatile("cp.async.commit_group;" ::: "memory")
#define CP_WAIT(N)  asm volatile("cp.async.wait_group %0;" :: "n"(N) : "memory")

// ===========================================================================
// Fused fp32->fp16 conversion (blocks 0..N-2) + mask compaction (last block).
// ===========================================================================
#define N4X (SQ * HIDN / 4)
#define N4W (HIDN * HIDN / 4)

__global__ __launch_bounds__(256)
void cvt_compact_kernel(const float* __restrict__ x,  const float* __restrict__ Wq,
                        const float* __restrict__ Wk, const float* __restrict__ Wv,
                        const int* __restrict__ mask)
{
    if (blockIdx.x == gridDim.x - 1) {
        __shared__ int wsum[8];
        const int t    = threadIdx.x;
        const int lane = t & 31;
        const int wid  = t >> 5;

        int mbits[16];
        int s = 0;
        #pragma unroll
        for (int i = 0; i < 16; i++) {
            int mm = mask[t * 16 + i] != 0;
            mbits[i] = mm;
            s += mm;
        }
        #pragma unroll
        for (int i = 0; i < 16; i++) g_idx[t * 16 + i] = 0;

        int sc = s;
        #pragma unroll
        for (int off = 1; off < 32; off <<= 1) {
            int v = __shfl_up_sync(0xffffffffu, sc, off);
            if (lane >= off) sc += v;
        }
        if (lane == 31) wsum[wid] = sc;
        __syncthreads();
        int wb = 0;
        for (int w = 0; w < wid; w++) wb += wsum[w];
        int pos = wb + sc - s;
        #pragma unroll
        for (int i = 0; i < 16; i++)
            if (mbits[i]) g_idx[pos++] = t * 16 + i;
        if (t == 255) g_nv = wb + sc;
        return;
    }

    const int nblk  = gridDim.x - 1;
    const int total = N4X + 3 * N4W;
    for (int idx = blockIdx.x * blockDim.x + threadIdx.x; idx < total;
         idx += nblk * blockDim.x) {
        const float* src; __half* dst; int off;
        if (idx < N4X)               { src = x;  dst = g_X;  off = idx; }
        else if (idx < N4X + N4W)    { src = Wq; dst = g_WQ; off = idx - N4X; }
        else if (idx < N4X + 2*N4W)  { src = Wk; dst = g_WK; off = idx - N4X - N4W; }
        else                         { src = Wv; dst = g_WV; off = idx - N4X - 2*N4W; }
        float4 v = ((const float4*)src)[off];
        __half2 h0 = __floats2half2_rn(v.x, v.y);
        __half2 h1 = __floats2half2_rn(v.z, v.w);
        ((uint2*)dst)[off] = make_uint2(*(uint32_t*)&h0, *(uint32_t*)&h1);
    }
}

// ===========================================================================
// QKV GEMM v3 (unchanged).
// grid = (16, 32, 3), 256 threads. BM=128, BN=64, BK=64. Warp tile 32x32.
// ===========================================================================
#define GST 72
#define G_ABUF 9216
#define G_WBUF 4608
#define GEMM_SMEM_BYTES ((3 * G_ABUF + 3 * G_WBUF) * 2)

__global__ __launch_bounds__(256, 2)
void qkv_mma_kernel(const float* __restrict__ bq,
                    const float* __restrict__ bk,
                    const float* __restrict__ bv)
{
    const __half* Wg;
    const float* bias;
    __half* Y;
    float oscale;
    if (blockIdx.z == 0)      { Wg = g_WQ; bias = bq; Y = g_Q; oscale = QSCALE; }
    else if (blockIdx.z == 1) { Wg = g_WK; bias = bk; Y = g_K; oscale = 1.0f; }
    else                      { Wg = g_WV; bias = bv; Y = g_V; oscale = 1.0f; }

    extern __shared__ __half gsm[];
    __half* Ab = gsm;
    __half* Wb = gsm + 3 * G_ABUF;

    const int t    = threadIdx.x;
    const int wid  = t >> 5;
    const int lane = t & 31;
    const int g    = lane >> 2;
    const int tg   = lane & 3;
    const int lm   = lane >> 3;
    const int lr   = lane & 7;

    const int rowBase = blockIdx.y * 128;
    const int colBase = blockIdx.x * 64;
    const int m0  = (wid >> 1) * 32;
    const int n0w = (wid & 1) * 32;

    const int srow = t >> 3;
    const int sc8  = (t & 7) * 8;

    const uint32_t aoff = (uint32_t)(((m0 + (lm & 1) * 8 + lr) * GST + (lm >> 1) * 8) * 2);
    const uint32_t boff = (uint32_t)((((lm & 1) * 8 + lr) * GST + n0w + (lm >> 1) * 8) * 2);

    float acc[2][4][4] = {};

    #define STG(buf, kk) do {                                                       \
        uint32_t ad = smem_u32(Ab + (buf) * G_ABUF);                                \
        uint32_t wd = smem_u32(Wb + (buf) * G_WBUF);                                \
        _Pragma("unroll")                                                           \
        for (int i_ = 0; i_ < 4; i_++) {                                            \
            int r_ = srow + i_ * 32;                                                \
            cp16(ad + (uint32_t)((r_ * GST + sc8) * 2),                             \
                 &g_X[(rowBase + r_) * HIDN + (kk) + sc8]);                         \
        }                                                                           \
        _Pragma("unroll")                                                           \
        for (int i_ = 0; i_ < 2; i_++) {                                            \
            int r_ = srow + i_ * 32;                                                \
            cp16(wd + (uint32_t)((r_ * GST + sc8) * 2),                             \
                 &Wg[((kk) + r_) * HIDN + colBase + sc8]);                          \
        }                                                                           \
    } while (0)

    STG(0, 0);  CP_COMMIT();
    STG(1, 64); CP_COMMIT();

    #pragma unroll 1
    for (int it = 0; it < HIDN / 64; it++) {
        const int buf = it % 3;
        CP_WAIT(1);
        __syncthreads();
        if (it + 2 < HIDN / 64) STG((it + 2) % 3, (it + 2) * 64);
        CP_COMMIT();

        const uint32_t ab = smem_u32(Ab + buf * G_ABUF) + aoff;
        const uint32_t bb = smem_u32(Wb + buf * G_WBUF) + boff;

        #pragma unroll
        for (int s = 0; s < 4; s++) {
            uint32_t a[2][4];
            #pragma unroll
            for (int mi = 0; mi < 2; mi++)
                ldsm_x4(a[mi][0], a[mi][1], a[mi][2], a[mi][3],
                        ab + (uint32_t)(((mi * 16) * GST + s * 16) * 2));
            #pragma unroll
            for (int j2 = 0; j2 < 2; j2++) {
                uint32_t b0, b1, b2, b3;
                ldsm_x4_t(b0, b1, b2, b3,
                          bb + (uint32_t)(((s * 16) * GST + j2 * 16) * 2));
                #pragma unroll
                for (int mi = 0; mi < 2; mi++) {
                    mma_f16(acc[mi][j2 * 2],     a[mi][0], a[mi][1], a[mi][2], a[mi][3], b0, b1);
                    mma_f16(acc[mi][j2 * 2 + 1], a[mi][0], a[mi][1], a[mi][2], a[mi][3], b2, b3);
                }
            }
        }
    }
    #undef STG

    #pragma unroll
    for (int mi = 0; mi < 2; mi++) {
        #pragma unroll
        for (int j = 0; j < 4; j++) {
            int c = colBase + n0w + j * 8 + 2 * tg;
            float2 bb = *(const float2*)&bias[c];
            int r0 = rowBase + m0 + mi * 16 + g;
            __half2 h0 = __floats2half2_rn((acc[mi][j][0] + bb.x) * oscale,
                                           (acc[mi][j][1] + bb.y) * oscale);
            __half2 h1 = __floats2half2_rn((acc[mi][j][2] + bb.x) * oscale,
                                           (acc[mi][j][3] + bb.y) * oscale);
            *(uint32_t*)&Y[r0 * HIDN + c]       = *(uint32_t*)&h0;
            *(uint32_t*)&Y[(r0 + 8) * HIDN + c] = *(uint32_t*)&h1;
        }
    }
}

// ===========================================================================
// Flash attention v12: 8 warps x 16 q-rows (128q CTA, halves staging traffic
// vs v11 at identical warp shape/occupancy), compacted keys via g_idx,
// fp32 __expf, mask only on tail tile. grid = (S/128, H), 256 thr, 2 CTA/SM.
// ===========================================================================
#define KST 72
#define F_KBUF 4608
#define FLASH_SMEM_BYTES (3 * F_KBUF * 2 * 2)

__global__ __launch_bounds__(256, 2)
void flash_mma(float* __restrict__ out)
{
    extern __shared__ char fsm[];
    __half* Kb = (__half*)fsm;                       // 3 x 4608 halfs
    __half* Vb = (__half*)(fsm + 3 * F_KBUF * 2);    // 3 x 4608 halfs

    const int t    = threadIdx.x;
    const int wid  = t >> 5;          // 0..7
    const int lane = t & 31;
    const int g    = lane >> 2;
    const int tg   = lane & 3;
    const int lm   = lane >> 3;
    const int lr   = lane & 7;
    const int h     = blockIdx.y;
    const int qBase = blockIdx.x * 128;
    const int m0    = wid * 16;

    const int srow = t >> 3;          // 0..31
    const int sc8  = (t & 7) * 8;

    const uint32_t koff = (uint32_t)((lr * KST + lm * 8) * 2);
    const uint32_t voff = (uint32_t)((((lm & 1) * 8 + lr) * KST + (lm >> 1) * 8) * 2);

    const int nv  = g_nv;
    const int nts = (nv + 63) >> 6;   // number of 64-key tiles

    // Q fragments, loop-invariant (pre-scaled by QSCALE in projection)
    uint32_t qa[4][4];
    {
        const __half* Q0 = &g_Q[(qBase + m0 + g) * HIDN + h * HD];
        const __half* Q1 = Q0 + 8 * HIDN;
        #pragma unroll
        for (int s = 0; s < 4; s++) {
            qa[s][0] = *(const uint32_t*)&Q0[s * 16 + 2 * tg];
            qa[s][1] = *(const uint32_t*)&Q1[s * 16 + 2 * tg];
            qa[s][2] = *(const uint32_t*)&Q0[s * 16 + 2 * tg + 8];
            qa[s][3] = *(const uint32_t*)&Q1[s * 16 + 2 * tg + 8];
        }
    }

    float oacc[8][4] = {};
    float ls[2] = {};

    // 256 threads stage 64 rows x 64 halfs per array: 2 cp16 per thread each
    #define STAGE(buf, kb) do {                                                     \
        uint32_t kdst = smem_u32(Kb + (buf) * F_KBUF);                              \
        uint32_t vdst = smem_u32(Vb + (buf) * F_KBUF);                              \
        _Pragma("unroll")                                                           \
        for (int i_ = 0; i_ < 2; i_++) {                                            \
            int row_ = srow + i_ * 32;                                              \
            int src_ = g_idx[(kb) + row_];                                          \
            cp16(kdst + (uint32_t)((row_ * KST + sc8) * 2),                         \
                 &g_K[src_ * HIDN + h * HD + sc8]);                                 \
            cp16(vdst + (uint32_t)((row_ * KST + sc8) * 2),                         \
                 &g_V[src_ * HIDN + h * HD + sc8]);                                 \
        }                                                                           \
    } while (0)

    STAGE(0, 0);  CP_COMMIT();
    STAGE(1, 64); CP_COMMIT();

    #pragma unroll 1
    for (int it = 0; it < nts; it++) {
        const int buf = it % 3;
        CP_WAIT(1);
        __syncthreads();
        if (it + 2 < nts) STAGE((it + 2) % 3, (it + 2) * 64);
        CP_COMMIT();

        const uint32_t kbase = smem_u32(Kb + buf * F_KBUF) + koff;
        const uint32_t vbase = smem_u32(Vb + buf * F_KBUF) + voff;
        const int kb = it * 64;
        const bool tail = (it == nts - 1);

        #pragma unroll
        for (int sp = 0; sp < 4; sp++) {
            float sacc[2][4] = {};
            uint32_t pa[4];

            #pragma unroll
            for (int jj = 0; jj < 2; jj++) {
                int j = sp * 2 + jj;
                uint32_t kl0, kl1, kl2, kl3, kh0, kh1, kh2, kh3;
                ldsm_x4(kl0, kl1, kl2, kl3, kbase + (uint32_t)((j * 8 * KST) * 2));
                ldsm_x4(kh0, kh1, kh2, kh3, kbase + (uint32_t)((j * 8 * KST + 32) * 2));
                mma_f16(sacc[jj], qa[0][0], qa[0][1], qa[0][2], qa[0][3], kl0, kl1);
                mma_f16(sacc[jj], qa[1][0], qa[1][1], qa[1][2], qa[1][3], kl2, kl3);
                mma_f16(sacc[jj], qa[2][0], qa[2][1], qa[2][2], qa[2][3], kh0, kh1);
                mma_f16(sacc[jj], qa[3][0], qa[3][1], qa[3][2], qa[3][3], kh2, kh3);
            }

            // softmax (fp32 __expf); positional mask only on tail tile
            #pragma unroll
            for (int jj = 0; jj < 2; jj++) {
                float s0 = sacc[jj][0], s1 = sacc[jj][1];
                float s2 = sacc[jj][2], s3 = sacc[jj][3];
                if (tail) {
                    int kc = kb + (sp * 2 + jj) * 8 + 2 * tg;
                    float mk0 = (kc     < nv) ? 0.f : NEGV;
                    float mk1 = (kc + 1 < nv) ? 0.f : NEGV;
                    s0 += mk0; s1 += mk1; s2 += mk0; s3 += mk1;
                }
                float p00 = __expf(s0);
                float p01 = __expf(s1);
                float p10 = __expf(s2);
                float p11 = __expf(s3);
                ls[0] += p00 + p01;
                ls[1] += p10 + p11;
                __half2 hA = __floats2half2_rn(p00, p01);   // row g
                __half2 hB = __floats2half2_rn(p10, p11);   // row g+8
                pa[jj * 2]     = *(uint32_t*)&hA;
                pa[jj * 2 + 1] = *(uint32_t*)&hB;
            }

            #pragma unroll
            for (int jd2 = 0; jd2 < 4; jd2++) {
                uint32_t v0, v1, v2, v3;
                ldsm_x4_t(v0, v1, v2, v3,
                          vbase + (uint32_t)(((sp * 16) * KST + jd2 * 16) * 2));
                mma_f16(oacc[jd2 * 2],     pa[0], pa[1], pa[2], pa[3], v0, v1);
                mma_f16(oacc[jd2 * 2 + 1], pa[0], pa[1], pa[2], pa[3], v2, v3);
            }
        }
    }
    #undef STAGE
    CP_WAIT(0);

    // Reduce l across the 4 lanes sharing a row, normalize, store
    #pragma unroll
    for (int off = 1; off <= 2; off <<= 1) {
        ls[0] += __shfl_xor_sync(0xffffffffu, ls[0], off);
        ls[1] += __shfl_xor_sync(0xffffffffu, ls[1], off);
    }
    float inv0 = 1.0f / ls[0];
    float inv1 = 1.0f / ls[1];
    float* o0 = &out[(qBase + m0 + g) * HIDN + h * HD];
    float* o1 = o0 + 8 * HIDN;
    #pragma unroll
    for (int jd = 0; jd < 8; jd++) {
        int dc = jd * 8 + 2 * tg;
        *(float2*)&o0[dc] = make_float2(oacc[jd][0] * inv0, oacc[jd][1] * inv0);
        *(float2*)&o1[dc] = make_float2(oacc[jd][2] * inv1, oacc[jd][3] * inv1);
    }
}

// ---------------------------------------------------------------------------
// kernel_launch
// Inputs: hidden_states, attention_mask, Wq, bq, Wk, bk, Wv, bv
// ---------------------------------------------------------------------------
extern "C" void kernel_launch(void* const* d_in, const int* in_sizes, int n_in,
                              void* d_out, int out_size)
{
    const float* x    = (const float*)d_in[0];
    const int*   msk  = (const int*)  d_in[1];
    const float* Wq   = (const float*)d_in[2];
    const float* bq   = (const float*)d_in[3];
    const float* Wk   = (const float*)d_in[4];
    const float* bk   = (const float*)d_in[5];
    const float* Wv   = (const float*)d_in[6];
    const float* bv   = (const float*)d_in[7];
    float* out = (float*)d_out;

    cudaFuncSetAttribute(qkv_mma_kernel,
                         cudaFuncAttributeMaxDynamicSharedMemorySize, GEMM_SMEM_BYTES);
    cudaFuncSetAttribute(flash_mma,
                         cudaFuncAttributeMaxDynamicSharedMemorySize, FLASH_SMEM_BYTES);

    cvt_compact_kernel<<<2049, 256>>>(x, Wq, Wk, Wv, msk);

    dim3 ggrid(HIDN / 64, SQ / 128, 3);
    qkv_mma_kernel<<<ggrid, 256, GEMM_SMEM_BYTES>>>(bq, bk, bv);

    dim3 agrid(SQ / 128, NH);
    flash_mma<<<agrid, 256, FLASH_SMEM_BYTES>>>(out);
}

// round 17
// speedup vs baseline: 1.4178x; 1.0750x over previous
#include <cuda_runtime.h>
#include <cuda_fp16.h>
#include <cstdint>

// Problem constants
#define SQ    4096
#define HIDN  1024
#define NH    16
#define HD    64
#define NEGV  -1e30f
#define QSCALE 0.125f

// fp16 copies of inputs (converted once per call)
__device__ __half g_X [SQ * HIDN];
__device__ __half g_WQ[HIDN * HIDN];
__device__ __half g_WK[HIDN * HIDN];
__device__ __half g_WV[HIDN * HIDN];
// Projection outputs
__device__ __half g_Q[SQ * HIDN];
__device__ __half g_K[SQ * HIDN];
__device__ __half g_V[SQ * HIDN];
// Mask compaction
__device__ int g_idx[SQ];
__device__ int g_nv;

__device__ __forceinline__ void mma_f16(float* c,
                                        uint32_t a0, uint32_t a1, uint32_t a2, uint32_t a3,
                                        uint32_t b0, uint32_t b1)
{
    asm volatile(
        "mma.sync.aligned.m16n8k16.row.col.f32.f16.f16.f32 "
        "{%0,%1,%2,%3}, {%4,%5,%6,%7}, {%8,%9}, {%0,%1,%2,%3};"
        : "+f"(c[0]), "+f"(c[1]), "+f"(c[2]), "+f"(c[3])
        : "r"(a0), "r"(a1), "r"(a2), "r"(a3), "r"(b0), "r"(b1));
}

__device__ __forceinline__ void ldsm_x4(uint32_t& r0, uint32_t& r1, uint32_t& r2, uint32_t& r3,
                                        uint32_t addr)
{
    asm volatile("ldmatrix.sync.aligned.m8n8.x4.shared.b16 {%0,%1,%2,%3}, [%4];"
                 : "=r"(r0), "=r"(r1), "=r"(r2), "=r"(r3) : "r"(addr));
}
__device__ __forceinline__ void ldsm_x4_t(uint32_t& r0, uint32_t& r1, uint32_t& r2, uint32_t& r3,
                                          uint32_t addr)
{
    asm volatile("ldmatrix.sync.aligned.m8n8.x4.trans.shared.b16 {%0,%1,%2,%3}, [%4];"
                 : "=r"(r0), "=r"(r1), "=r"(r2), "=r"(r3) : "r"(addr));
}
__device__ __forceinline__ uint32_t smem_u32(const void* p) {
    uint32_t a;
    asm("{ .reg .u64 t; cvta.to.shared.u64 t, %1; cvt.u32.u64 %0, t; }" : "=r"(a) : "l"(p));
    return a;
}
__device__ __forceinline__ void cp16(uint32_t saddr, const void* g) {
    asm volatile("cp.async.cg.shared.global [%0], [%1], 16;" :: "r"(saddr), "l"(g));
}
#define CP_COMMIT() asm volatile("cp.async.commit_group;" ::: "memory")
#define CP_WAIT(N)  asm volatile("cp.async.wait_group %0;" :: "n"(N) : "memory")

// ===========================================================================
// Fused fp32->fp16 conversion (blocks 0..N-2) + mask compaction (last block).
// ===========================================================================
#define N4X (SQ * HIDN / 4)
#define N4W (HIDN * HIDN / 4)

__global__ __launch_bounds__(256)
void cvt_compact_kernel(const float* __restrict__ x,  const float* __restrict__ Wq,
                        const float* __restrict__ Wk, const float* __restrict__ Wv,
                        const int* __restrict__ mask)
{
    if (blockIdx.x == gridDim.x - 1) {
        __shared__ int wsum[8];
        const int t    = threadIdx.x;
        const int lane = t & 31;
        const int wid  = t >> 5;

        int mbits[16];
        int s = 0;
        #pragma unroll
        for (int i = 0; i < 16; i++) {
            int mm = mask[t * 16 + i] != 0;
            mbits[i] = mm;
            s += mm;
        }
        #pragma unroll
        for (int i = 0; i < 16; i++) g_idx[t * 16 + i] = 0;

        int sc = s;
        #pragma unroll
        for (int off = 1; off < 32; off <<= 1) {
            int v = __shfl_up_sync(0xffffffffu, sc, off);
            if (lane >= off) sc += v;
        }
        if (lane == 31) wsum[wid] = sc;
        __syncthreads();
        int wb = 0;
        for (int w = 0; w < wid; w++) wb += wsum[w];
        int pos = wb + sc - s;
        #pragma unroll
        for (int i = 0; i < 16; i++)
            if (mbits[i]) g_idx[pos++] = t * 16 + i;
        if (t == 255) g_nv = wb + sc;
        return;
    }

    const int nblk  = gridDim.x - 1;
    const int total = N4X + 3 * N4W;
    for (int idx = blockIdx.x * blockDim.x + threadIdx.x; idx < total;
         idx += nblk * blockDim.x) {
        const float* src; __half* dst; int off;
        if (idx < N4X)               { src = x;  dst = g_X;  off = idx; }
        else if (idx < N4X + N4W)    { src = Wq; dst = g_WQ; off = idx - N4X; }
        else if (idx < N4X + 2*N4W)  { src = Wk; dst = g_WK; off = idx - N4X - N4W; }
        else                         { src = Wv; dst = g_WV; off = idx - N4X - 2*N4W; }
        float4 v = ((const float4*)src)[off];
        __half2 h0 = __floats2half2_rn(v.x, v.y);
        __half2 h1 = __floats2half2_rn(v.z, v.w);
        ((uint2*)dst)[off] = make_uint2(*(uint32_t*)&h0, *(uint32_t*)&h1);
    }
}

// ===========================================================================
// QKV GEMM v5: BM=128, BN=128, BK=64, warp tile 32x64 (4x2 warp grid),
// 3-stage cp.async ring. grid = (8, 32, 3), 256 threads, 2 CTA/SM.
// ===========================================================================
#define AST 72     // A smem row stride (halfs)
#define WST 136    // W smem row stride (halfs); LDSM-T rows -> banks 4r
#define G_ABUF (128 * AST)   // 9216 halfs
#define G_WBUF (64 * WST)    // 8704 halfs
#define GEMM_SMEM_BYTES (3 * (G_ABUF + G_WBUF) * 2)   // 107520

__global__ __launch_bounds__(256, 2)
void qkv_mma_kernel(const float* __restrict__ bq,
                    const float* __restrict__ bk,
                    const float* __restrict__ bv)
{
    const __half* Wg;
    const float* bias;
    __half* Y;
    float oscale;
    if (blockIdx.z == 0)      { Wg = g_WQ; bias = bq; Y = g_Q; oscale = QSCALE; }
    else if (blockIdx.z == 1) { Wg = g_WK; bias = bk; Y = g_K; oscale = 1.0f; }
    else                      { Wg = g_WV; bias = bv; Y = g_V; oscale = 1.0f; }

    extern __shared__ __half gsm[];
    __half* Ab = gsm;                         // 3 x G_ABUF
    __half* Wb = gsm + 3 * G_ABUF;            // 3 x G_WBUF

    const int t    = threadIdx.x;
    const int wid  = t >> 5;
    const int lane = t & 31;
    const int g    = lane >> 2;
    const int tg   = lane & 3;
    const int lm   = lane >> 3;
    const int lr   = lane & 7;

    const int rowBase = blockIdx.y * 128;
    const int colBase = blockIdx.x * 128;
    const int m0  = (wid >> 1) * 32;          // warp rows (4 row-groups)
    const int n0w = (wid & 1) * 64;           // warp cols (2 col-groups)

    // A staging coords: 128 rows x 64 halfs
    const int srow = t >> 3;                  // 0..31
    const int sc8  = (t & 7) * 8;
    // W staging coords: 64 rows x 128 halfs
    const int wrow = t >> 4;                  // 0..15
    const int wc8  = (t & 15) * 8;

    const uint32_t aoff = (uint32_t)(((m0 + (lm & 1) * 8 + lr) * AST + (lm >> 1) * 8) * 2);
    const uint32_t boff = (uint32_t)((((lm & 1) * 8 + lr) * WST + n0w + (lm >> 1) * 8) * 2);

    float acc[2][8][4] = {};

    #define STG(buf, kk) do {                                                       \
        uint32_t ad = smem_u32(Ab + (buf) * G_ABUF);                                \
        uint32_t wd = smem_u32(Wb + (buf) * G_WBUF);                                \
        _Pragma("unroll")                                                           \
        for (int i_ = 0; i_ < 4; i_++) {                                            \
            int r_ = srow + i_ * 32;                                                \
            cp16(ad + (uint32_t)((r_ * AST + sc8) * 2),                             \
                 &g_X[(rowBase + r_) * HIDN + (kk) + sc8]);                         \
        }                                                                           \
        _Pragma("unroll")                                                           \
        for (int i_ = 0; i_ < 4; i_++) {                                            \
            int r_ = wrow + i_ * 16;                                                \
            cp16(wd + (uint32_t)((r_ * WST + wc8) * 2),                             \
                 &Wg[((kk) + r_) * HIDN + colBase + wc8]);                          \
        }                                                                           \
    } while (0)

    STG(0, 0);  CP_COMMIT();
    STG(1, 64); CP_COMMIT();

    #pragma unroll 1
    for (int it = 0; it < HIDN / 64; it++) {
        const int buf = it % 3;
        CP_WAIT(1);
        __syncthreads();
        if (it + 2 < HIDN / 64) STG((it + 2) % 3, (it + 2) * 64);
        CP_COMMIT();

        const uint32_t ab = smem_u32(Ab + buf * G_ABUF) + aoff;
        const uint32_t bb = smem_u32(Wb + buf * G_WBUF) + boff;

        #pragma unroll
        for (int s = 0; s < 4; s++) {
            uint32_t a[2][4];
            #pragma unroll
            for (int mi = 0; mi < 2; mi++)
                ldsm_x4(a[mi][0], a[mi][1], a[mi][2], a[mi][3],
                        ab + (uint32_t)(((mi * 16) * AST + s * 16) * 2));
            #pragma unroll
            for (int j2 = 0; j2 < 4; j2++) {
                uint32_t b0, b1, b2, b3;
                ldsm_x4_t(b0, b1, b2, b3,
                          bb + (uint32_t)(((s * 16) * WST + j2 * 16) * 2));
                #pragma unroll
                for (int mi = 0; mi < 2; mi++) {
                    mma_f16(acc[mi][j2 * 2],     a[mi][0], a[mi][1], a[mi][2], a[mi][3], b0, b1);
                    mma_f16(acc[mi][j2 * 2 + 1], a[mi][0], a[mi][1], a[mi][2], a[mi][3], b2, b3);
                }
            }
        }
    }
    #undef STG

    #pragma unroll
    for (int mi = 0; mi < 2; mi++) {
        #pragma unroll
        for (int j = 0; j < 8; j++) {
            int c = colBase + n0w + j * 8 + 2 * tg;
            float2 bb = *(const float2*)&bias[c];
            int r0 = rowBase + m0 + mi * 16 + g;
            __half2 h0 = __floats2half2_rn((acc[mi][j][0] + bb.x) * oscale,
                                           (acc[mi][j][1] + bb.y) * oscale);
            __half2 h1 = __floats2half2_rn((acc[mi][j][2] + bb.x) * oscale,
                                           (acc[mi][j][3] + bb.y) * oscale);
            *(uint32_t*)&Y[r0 * HIDN + c]       = *(uint32_t*)&h0;
            *(uint32_t*)&Y[(r0 + 8) * HIDN + c] = *(uint32_t*)&h1;
        }
    }
}

// ===========================================================================
// Flash attention v12 (unchanged): 8 warps x 16 q-rows, compacted keys via
// g_idx, fp32 __expf, mask only on tail tile. grid = (S/128, H), 256 thr.
// ===========================================================================
#define KST 72
#define F_KBUF 4608
#define FLASH_SMEM_BYTES (3 * F_KBUF * 2 * 2)

__global__ __launch_bounds__(256, 2)
void flash_mma(float* __restrict__ out)
{
    extern __shared__ char fsm[];
    __half* Kb = (__half*)fsm;                       // 3 x 4608 halfs
    __half* Vb = (__half*)(fsm + 3 * F_KBUF * 2);    // 3 x 4608 halfs

    const int t    = threadIdx.x;
    const int wid  = t >> 5;          // 0..7
    const int lane = t & 31;
    const int g    = lane >> 2;
    const int tg   = lane & 3;
    const int lm   = lane >> 3;
    const int lr   = lane & 7;
    const int h     = blockIdx.y;
    const int qBase = blockIdx.x * 128;
    const int m0    = wid * 16;

    const int srow = t >> 3;          // 0..31
    const int sc8  = (t & 7) * 8;

    const uint32_t koff = (uint32_t)((lr * KST + lm * 8) * 2);
    const uint32_t voff = (uint32_t)((((lm & 1) * 8 + lr) * KST + (lm >> 1) * 8) * 2);

    const int nv  = g_nv;
    const int nts = (nv + 63) >> 6;   // number of 64-key tiles

    // Q fragments, loop-invariant (pre-scaled by QSCALE in projection)
    uint32_t qa[4][4];
    {
        const __half* Q0 = &g_Q[(qBase + m0 + g) * HIDN + h * HD];
        const __half* Q1 = Q0 + 8 * HIDN;
        #pragma unroll
        for (int s = 0; s < 4; s++) {
            qa[s][0] = *(const uint32_t*)&Q0[s * 16 + 2 * tg];
            qa[s][1] = *(const uint32_t*)&Q1[s * 16 + 2 * tg];
            qa[s][2] = *(const uint32_t*)&Q0[s * 16 + 2 * tg + 8];
            qa[s][3] = *(const uint32_t*)&Q1[s * 16 + 2 * tg + 8];
        }
    }

    float oacc[8][4] = {};
    float ls[2] = {};

    #define STAGE(buf, kb) do {                                                     \
        uint32_t kdst = smem_u32(Kb + (buf) * F_KBUF);                              \
        uint32_t vdst = smem_u32(Vb + (buf) * F_KBUF);                              \
        _Pragma("unroll")                                                           \
        for (int i_ = 0; i_ < 2; i_++) {                                            \
            int row_ = srow + i_ * 32;                                              \
            int src_ = g_idx[(kb) + row_];                                          \
            cp16(kdst + (uint32_t)((row_ * KST + sc8) * 2),                         \
                 &g_K[src_ * HIDN + h * HD + sc8]);                                 \
            cp16(vdst + (uint32_t)((row_ * KST + sc8) * 2),                         \
                 &g_V[src_ * HIDN + h * HD + sc8]);                                 \
        }                                                                           \
    } while (0)

    STAGE(0, 0);  CP_COMMIT();
    STAGE(1, 64); CP_COMMIT();

    #pragma unroll 1
    for (int it = 0; it < nts; it++) {
        const int buf = it % 3;
        CP_WAIT(1);
        __syncthreads();
        if (it + 2 < nts) STAGE((it + 2) % 3, (it + 2) * 64);
        CP_COMMIT();

        const uint32_t kbase = smem_u32(Kb + buf * F_KBUF) + koff;
        const uint32_t vbase = smem_u32(Vb + buf * F_KBUF) + voff;
        const int kb = it * 64;
        const bool tail = (it == nts - 1);

        #pragma unroll
        for (int sp = 0; sp < 4; sp++) {
            float sacc[2][4] = {};
            uint32_t pa[4];

            #pragma unroll
            for (int jj = 0; jj < 2; jj++) {
                int j = sp * 2 + jj;
                uint32_t kl0, kl1, kl2, kl3, kh0, kh1, kh2, kh3;
                ldsm_x4(kl0, kl1, kl2, kl3, kbase + (uint32_t)((j * 8 * KST) * 2));
                ldsm_x4(kh0, kh1, kh2, kh3, kbase + (uint32_t)((j * 8 * KST + 32) * 2));
                mma_f16(sacc[jj], qa[0][0], qa[0][1], qa[0][2], qa[0][3], kl0, kl1);
                mma_f16(sacc[jj], qa[1][0], qa[1][1], qa[1][2], qa[1][3], kl2, kl3);
                mma_f16(sacc[jj], qa[2][0], qa[2][1], qa[2][2], qa[2][3], kh0, kh1);
                mma_f16(sacc[jj], qa[3][0], qa[3][1], qa[3][2], qa[3][3], kh2, kh3);
            }

            // softmax (fp32 __expf); positional mask only on tail tile
            #pragma unroll
            for (int jj = 0; jj < 2; jj++) {
                float s0 = sacc[jj][0], s1 = sacc[jj][1];
                float s2 = sacc[jj][2], s3 = sacc[jj][3];
                if (tail) {
                    int kc = kb + (sp * 2 + jj) * 8 + 2 * tg;
                    float mk0 = (kc     < nv) ? 0.f : NEGV;
                    float mk1 = (kc + 1 < nv) ? 0.f : NEGV;
                    s0 += mk0; s1 += mk1; s2 += mk0; s3 += mk1;
                }
                float p00 = __expf(s0);
                float p01 = __expf(s1);
                float p10 = __expf(s2);
                float p11 = __expf(s3);
                ls[0] += p00 + p01;
                ls[1] += p10 + p11;
                __half2 hA = __floats2half2_rn(p00, p01);   // row g
                __half2 hB = __floats2half2_rn(p10, p11);   // row g+8
                pa[jj * 2]     = *(uint32_t*)&hA;
                pa[jj * 2 + 1] = *(uint32_t*)&hB;
            }

            #pragma unroll
            for (int jd2 = 0; jd2 < 4; jd2++) {
                uint32_t v0, v1, v2, v3;
                ldsm_x4_t(v0, v1, v2, v3,
                          vbase + (uint32_t)(((sp * 16) * KST + jd2 * 16) * 2));
                mma_f16(oacc[jd2 * 2],     pa[0], pa[1], pa[2], pa[3], v0, v1);
                mma_f16(oacc[jd2 * 2 + 1], pa[0], pa[1], pa[2], pa[3], v2, v3);
            }
        }
    }
    #undef STAGE
    CP_WAIT(0);

    // Reduce l across the 4 lanes sharing a row, normalize, store
    #pragma unroll
    for (int off = 1; off <= 2; off <<= 1) {
        ls[0] += __shfl_xor_sync(0xffffffffu, ls[0], off);
        ls[1] += __shfl_xor_sync(0xffffffffu, ls[1], off);
    }
    float inv0 = 1.0f / ls[0];
    float inv1 = 1.0f / ls[1];
    float* o0 = &out[(qBase + m0 + g) * HIDN + h * HD];
    float* o1 = o0 + 8 * HIDN;
    #pragma unroll
    for (int jd = 0; jd < 8; jd++) {
        int dc = jd * 8 + 2 * tg;
        *(float2*)&o0[dc] = make_float2(oacc[jd][0] * inv0, oacc[jd][1] * inv0);
        *(float2*)&o1[dc] = make_float2(oacc[jd][2] * inv1, oacc[jd][3] * inv1);
    }
}

// ---------------------------------------------------------------------------
// kernel_launch
// Inputs: hidden_states, attention_mask, Wq, bq, Wk, bk, Wv, bv
// ---------------------------------------------------------------------------
extern "C" void kernel_launch(void* const* d_in, const int* in_sizes, int n_in,
                              void* d_out, int out_size)
{
    const float* x    = (const float*)d_in[0];
    const int*   msk  = (const int*)  d_in[1];
    const float* Wq   = (const float*)d_in[2];
    const float* bq   = (const float*)d_in[3];
    const float* Wk   = (const float*)d_in[4];
    const float* bk   = (const float*)d_in[5];
    const float* Wv   = (const float*)d_in[6];
    const float* bv   = (const float*)d_in[7];
    float* out = (float*)d_out;

    cudaFuncSetAttribute(qkv_mma_kernel,
                         cudaFuncAttributeMaxDynamicSharedMemorySize, GEMM_SMEM_BYTES);
    cudaFuncSetAttribute(flash_mma,
                         cudaFuncAttributeMaxDynamicSharedMemorySize, FLASH_SMEM_BYTES);

    cvt_compact_kernel<<<2049, 256>>>(x, Wq, Wk, Wv, msk);

    dim3 ggrid(HIDN / 128, SQ / 128, 3);
    qkv_mma_kernel<<<ggrid, 256, GEMM_SMEM_BYTES>>>(bq, bk, bv);

    dim3 agrid(SQ / 128, NH);
    flash_mma<<<agrid, 256, FLASH_SMEM_BYTES>>>(out);
}